// round 2
// baseline (speedup 1.0000x reference)
#include <cuda_runtime.h>
#include <math.h>

#define SB 8
#define CH 32
#define KM 32
#define OC 32
#define SS 2048
#define DF (1.0f/2047.0f)

// ---- scratch (device globals: allocation-free rule) ----
__device__ float g_xsum[SB*SS];        // [b][s]
__device__ float g_cpart[64*CH];       // per-block per-channel partial sums
__device__ float g_P[(size_t)SB*SS*KM];// [b][t][k] forward decay scan
__device__ float g_Q[(size_t)SB*SS*KM];// [b][t][k] backward decay scan
__device__ float g_wsum[KM*OC];        // [k][o]
__device__ float g_invnf[SS*KM];       // [t][k] filter/rownorm
__device__ float g_coefL[SS*KM];       // [t][k] a^(mL+1)
__device__ float g_coefR[SS*KM];       // [t][k] a^(mR+1)
__device__ int   g_mL[SS], g_mR[SS];
__device__ float g_a[KM], g_aG[KM];

// replicate reference float32 coords: linspace(0,1,2048), endpoint forced
__device__ __forceinline__ float coordf(int i) {
    return (i == SS - 1) ? 1.0f : ((float)i) * DF;
}

// ---------------- Stage 0: xsum[b][s] = sum_c x ; per-channel partials ----------------
__global__ __launch_bounds__(256) void k_pre(const float* __restrict__ x) {
    int b  = blockIdx.x >> 3;
    int sc = blockIdx.x & 7;
    int tid = threadIdx.x;
    int wid = tid >> 5;
    int s = sc * 256 + tid;
    __shared__ float smc[CH][8];
    float acc = 0.f;
    #pragma unroll 4
    for (int c = 0; c < CH; c++) {
        float v = x[((size_t)(b * CH + c)) * SS + s];
        acc += v;
        // warp-reduce v for the channel partial
        float w = v;
        w += __shfl_xor_sync(0xffffffffu, w, 16);
        w += __shfl_xor_sync(0xffffffffu, w, 8);
        w += __shfl_xor_sync(0xffffffffu, w, 4);
        w += __shfl_xor_sync(0xffffffffu, w, 2);
        w += __shfl_xor_sync(0xffffffffu, w, 1);
        if ((tid & 31) == 0) smc[c][wid] = w;
    }
    g_xsum[b * SS + s] = acc;
    __syncthreads();
    if (tid < CH) {
        float t = 0.f;
        #pragma unroll
        for (int w = 0; w < 8; w++) t += smc[tid][w];
        g_cpart[blockIdx.x * CH + tid] = t;
    }
}

// ---------------- Stage 1: poles, exact windows, coefs, wsum ----------------
__global__ __launch_bounds__(1024) void k_setup(
    const float* __restrict__ c_star, const float* __restrict__ dt_star,
    const float* __restrict__ wla, const float* __restrict__ wph,
    const float* __restrict__ log_poles, const float* __restrict__ pole_w,
    const float* __restrict__ pole_b)
{
    __shared__ float sh_xmean[CH];
    __shared__ float sh_poles[KM];
    __shared__ float shD;
    int tid = threadIdx.x;

    if (tid == 0) {
        float mx = c_star[0];
        for (int i = 1; i < SB; i++) mx = fmaxf(mx, c_star[i]);
        shD = mx * dt_star[0];                 // CAUSAL_SAFETY = 1
    }
    if (tid < CH) {
        float s = 0.f;
        for (int blk = 0; blk < 64; blk++) s += g_cpart[blk * CH + tid];
        sh_xmean[tid] = s / (float)(SB * SS);
    }
    __syncthreads();
    float D = shD;

    if (tid < KM) {
        int k = tid;
        float off = 0.f;
        for (int c = 0; c < CH; c++) off += sh_xmean[c] * pole_w[c * KM + k];
        off = tanhf(off + pole_b[k]);
        float v = log_poles[k] + 0.1f * off;
        float sp = fmaxf(v, 0.f) + log1pf(expf(-fabsf(v)));   // softplus (logaddexp form)
        float p = fminf(fmaxf(sp, 0.1f), 100.f);
        sh_poles[k] = p;
        g_a[k]  = expf(-p * DF);
        g_aG[k] = expf(-p * DF * 64.f);
    }

    // exact per-row window sizes, replicating float32 comparisons
    for (int t = tid; t < SS; t += 1024) {
        float ct = coordf(t);
        int guess = (int)(D * 2047.0f) + 2;
        // right side
        int hi = SS - 1 - t;
        int j = min(hi, max(0, guess));
        while (j > 0 && fabsf(coordf(t + j) - ct) > D) j--;
        while (j < hi && fabsf(coordf(t + j + 1) - ct) <= D) j++;
        g_mR[t] = j;
        // left side
        hi = t;
        j = min(hi, max(0, guess));
        while (j > 0 && fabsf(coordf(t - j) - ct) > D) j--;
        while (j < hi && fabsf(coordf(t - j - 1) - ct) <= D) j++;
        g_mL[t] = j;
    }
    __syncthreads();

    // invnf and window coefficients
    for (int i = tid; i < SS * KM; i += 1024) {
        int t = i >> 5, k = i & 31;
        float ph = sh_poles[k] * DF;
        int mL = g_mL[t], mR = g_mR[t];
        float em = expm1f(-ph);
        float GL = expm1f(-ph * (float)(mL + 1)) / em;  // sum_{j=0}^{mL} a^j
        float GR = expm1f(-ph * (float)(mR + 1)) / em;
        float norm = fmaxf(GL + GR - 1.f, 1e-8f);
        float kn = (float)k * (1.0f / (float)(KM - 1));
        float filt = expf(-4.f * kn * kn);
        g_invnf[i] = filt / norm;
        g_coefL[i] = expf(-ph * (float)(mL + 1));
        g_coefR[i] = expf(-ph * (float)(mR + 1));
    }

    // wsum[k][o] = sum_c sigmoid(wla) * cos(wph)
    {
        int k = tid >> 5, o = tid & 31;
        float s = 0.f;
        for (int c = 0; c < CH; c++) {
            int idx = (k * CH + c) * OC + o;
            float amp = 1.f / (1.f + expf(-wla[idx]));
            s += amp * cosf(wph[idx]);
        }
        g_wsum[k * OC + o] = s;
    }
}

// ---------------- Stage 2: chunk-parallel decay scans P (fwd) and Q (bwd) ----------------
__global__ __launch_bounds__(1024) void k_scan() {
    __shared__ float xs[SS];
    __shared__ float lc[32 * 32];
    __shared__ float rc[32 * 32];
    int b = blockIdx.x;
    int tid = threadIdx.x;
    for (int i = tid; i < SS; i += 1024) xs[i] = g_xsum[b * SS + i];

    int j = tid >> 5, k = tid & 31;      // warp = chunk, lane = mode
    float a = g_a[k], aG = g_aG[k];
    int t0 = j * 64;
    __syncthreads();

    // pass 1: chunk-local carries (seed 0)
    float l = 0.f, r = 0.f;
    #pragma unroll
    for (int i = 0; i < 64; i++) l = fmaf(a, l, xs[t0 + i]);
    #pragma unroll
    for (int i = 63; i >= 0; i--) r = fmaf(a, r, xs[t0 + i]);
    lc[j * 32 + k] = l;
    rc[j * 32 + k] = r;
    __syncthreads();

    // serial combine of carries (warp 0 fwd, warp 1 bwd), exclusive -> incoming state
    if (j == 0) {
        float s = 0.f;
        for (int q = 0; q < 32; q++) { float tmp = lc[q * 32 + k]; lc[q * 32 + k] = s; s = fmaf(aG, s, tmp); }
    }
    if (j == 1) {
        float s = 0.f;
        for (int q = 31; q >= 0; q--) { float tmp = rc[q * 32 + k]; rc[q * 32 + k] = s; s = fmaf(aG, s, tmp); }
    }
    __syncthreads();

    // pass 2: seeded scans, write P/Q
    float* Pb = g_P + (size_t)b * SS * KM;
    float* Qb = g_Q + (size_t)b * SS * KM;
    l = lc[j * 32 + k];
    #pragma unroll
    for (int i = 0; i < 64; i++) {
        l = fmaf(a, l, xs[t0 + i]);
        Pb[(size_t)(t0 + i) * KM + k] = l;
    }
    r = rc[j * 32 + k];
    #pragma unroll
    for (int i = 63; i >= 0; i--) {
        r = fmaf(a, r, xs[t0 + i]);
        Qb[(size_t)(t0 + i) * KM + k] = r;
    }
}

// ---------------- Stage 3: gather windows, build z tile, GEMV vs wsum ----------------
__global__ __launch_bounds__(256) void k_out(float* __restrict__ out) {
    __shared__ float zt[128 * 32];     // [tl][k]
    __shared__ float ws[KM * OC];      // [k][o]
    __shared__ float st[128 * 33];     // [tl][o] padded
    int tc = blockIdx.x, b = blockIdx.y;
    int t0 = tc * 128;
    int tid = threadIdx.x;
    int w = tid >> 5, lane = tid & 31;

    for (int i = tid; i < KM * OC; i += 256) ws[i] = g_wsum[i];

    const float* Pb = g_P + (size_t)b * SS * KM;
    const float* Qb = g_Q + (size_t)b * SS * KM;
    float a = g_a[lane];

    // phase A: z tile. warp w handles rows tl = w, w+8, ...; lane = k
    #pragma unroll 4
    for (int q = 0; q < 16; q++) {
        int tl = w + 8 * q;
        int t = t0 + tl;
        int mL = g_mL[t], mR = g_mR[t];
        float P  = Pb[(size_t)t * KM + lane];
        int tm = t - mL - 1;
        float Pm = (tm >= 0) ? Pb[(size_t)tm * KM + lane] : 0.f;
        float Qp = (t + 1 < SS) ? Qb[(size_t)(t + 1) * KM + lane] : 0.f;
        int tp = t + mR + 1;
        float Qm = (tp < SS) ? Qb[(size_t)tp * KM + lane] : 0.f;
        float L = fmaf(-g_coefL[t * KM + lane], Pm, P);
        float R = fmaf(-g_coefR[t * KM + lane], Qm, a * Qp);
        zt[tl * 32 + lane] = (L + R) * g_invnf[t * KM + lane];
    }
    __syncthreads();

    // phase B: out(tl, o) = sum_k zt[tl][k] * ws[k][o]; warp w -> rows w*16..w*16+15, lane = o
    #pragma unroll 2
    for (int q = 0; q < 16; q++) {
        int tl = w * 16 + q;
        const float4* zr = (const float4*)(zt + tl * 32);
        float acc = 0.f;
        #pragma unroll
        for (int p = 0; p < 8; p++) {
            float4 zv = zr[p];                    // lane-uniform broadcast
            acc = fmaf(zv.x, ws[(p * 4 + 0) * OC + lane], acc);
            acc = fmaf(zv.y, ws[(p * 4 + 1) * OC + lane], acc);
            acc = fmaf(zv.z, ws[(p * 4 + 2) * OC + lane], acc);
            acc = fmaf(zv.w, ws[(p * 4 + 3) * OC + lane], acc);
        }
        st[tl * 33 + lane] = acc;
    }
    __syncthreads();

    // coalesced-ish store: thread -> (o = tid/8, 16 consecutive t)
    int o = tid >> 3;
    int i0 = (tid & 7) * 16;
    float* op = out + ((size_t)(b * OC + o)) * SS + t0 + i0;
    #pragma unroll
    for (int ii = 0; ii < 16; ii++) op[ii] = st[(i0 + ii) * 33 + o];
}

extern "C" void kernel_launch(void* const* d_in, const int* in_sizes, int n_in,
                              void* d_out, int out_size) {
    // size-based input resolution (robust to dict-order vs alphabetical metadata)
    int ix = -1, ic = -1, idt = -1, iwla = -1, iwph = -1, ilp = -1, ipw = -1, ipb = -1;
    for (int i = 0; i < n_in; i++) {
        int s = in_sizes[i];
        if (s == SB * CH * SS)      { if (ix  < 0) ix  = i; }
        else if (s == SB)           { if (ic  < 0) ic  = i; }
        else if (s == KM * CH * OC) { if (iwla < 0) iwla = i; else if (iwph < 0) iwph = i; }
        else if (s == CH * KM)      { if (ipw < 0) ipw = i; }
        else if (s == KM)           { if (ilp < 0) ilp = i; else if (ipb < 0) ipb = i; }
        else if (s == 1)            { if (idt < 0) idt = i; }   // dt_star precedes dx_star in both orders
    }
    const float* x   = (const float*)d_in[ix];
    const float* cs  = (const float*)d_in[ic];
    const float* dt  = (const float*)d_in[idt];
    const float* wla = (const float*)d_in[iwla];
    const float* wph = (const float*)d_in[iwph];
    const float* lp  = (const float*)d_in[ilp];
    const float* pw  = (const float*)d_in[ipw];
    const float* pb  = (const float*)d_in[ipb];
    float* out = (float*)d_out;

    k_pre<<<64, 256>>>(x);
    k_setup<<<1, 1024>>>(cs, dt, wla, wph, lp, pw, pb);
    k_scan<<<SB, 1024>>>();
    k_out<<<dim3(SS / 128, SB), 256>>>(out);
}

// round 3
// speedup vs baseline: 2.3905x; 2.3905x over previous
#include <cuda_runtime.h>
#include <math.h>

#define SB 8
#define CH 32
#define KM 32
#define OC 32
#define SS 2048
#define DF (1.0f/2047.0f)

// ---- scratch (device globals: allocation-free rule) ----
__device__ float g_xsum[SB*SS];          // [b][s]
__device__ float g_cpart[64*CH];         // per-block per-channel partials
__device__ float g_P[(size_t)SB*SS*KM];  // [b][t][k] forward decay scan
__device__ float g_Q[(size_t)SB*SS*KM];  // [b][t][k] backward decay scan
__device__ float g_wsum[KM*OC];          // [k][o]
__device__ float4 g_pack[SS*KM];         // [t][k]: (coefL, coefR, invnf, bits(mL|mR<<16))
__device__ float g_a[KM], g_aG[KM], g_poles[KM];
__device__ float g_D;

// replicate reference float32 coords: linspace(0,1,2048)
__device__ __forceinline__ float coordf(int i) {
    return (i == SS - 1) ? 1.0f : ((float)i) * DF;
}

// ---------------- Stage 0: xsum[b][s] ; per-channel partials ----------------
__global__ __launch_bounds__(256) void k_pre(const float* __restrict__ x) {
    int b  = blockIdx.x >> 3;
    int sc = blockIdx.x & 7;
    int tid = threadIdx.x;
    int wid = tid >> 5;
    int s = sc * 256 + tid;
    __shared__ float smc[CH][8];
    float acc = 0.f;
    #pragma unroll 4
    for (int c = 0; c < CH; c++) {
        float v = x[((size_t)(b * CH + c)) * SS + s];
        acc += v;
        float w = v;
        w += __shfl_xor_sync(0xffffffffu, w, 16);
        w += __shfl_xor_sync(0xffffffffu, w, 8);
        w += __shfl_xor_sync(0xffffffffu, w, 4);
        w += __shfl_xor_sync(0xffffffffu, w, 2);
        w += __shfl_xor_sync(0xffffffffu, w, 1);
        if ((tid & 31) == 0) smc[c][wid] = w;
    }
    g_xsum[b * SS + s] = acc;
    __syncthreads();
    if (tid < CH) {
        float t = 0.f;
        #pragma unroll
        for (int w = 0; w < 8; w++) t += smc[tid][w];
        g_cpart[blockIdx.x * CH + tid] = t;
    }
}

// ---------------- Stage 1a: D, x_mean -> poles, a, a^64 (tiny) ----------------
__global__ __launch_bounds__(32) void k_poles(
    const float* __restrict__ c_star, const float* __restrict__ dt_star,
    const float* __restrict__ log_poles, const float* __restrict__ pole_w,
    const float* __restrict__ pole_b)
{
    __shared__ float sh_xmean[CH];
    int tid = threadIdx.x;
    if (tid == 0) {
        float mx = c_star[0];
        for (int i = 1; i < SB; i++) mx = fmaxf(mx, c_star[i]);
        g_D = mx * dt_star[0];                 // CAUSAL_SAFETY = 1
    }
    {
        float s = 0.f;
        #pragma unroll 8
        for (int blk = 0; blk < 64; blk++) s += g_cpart[blk * CH + tid];
        sh_xmean[tid] = s / (float)(SB * SS);
    }
    __syncwarp();
    int k = tid;
    float off = 0.f;
    #pragma unroll 8
    for (int c = 0; c < CH; c++) off += sh_xmean[c] * pole_w[c * KM + k];
    off = tanhf(off + pole_b[k]);
    float v = log_poles[k] + 0.1f * off;
    float sp = fmaxf(v, 0.f) + log1pf(expf(-fabsf(v)));   // softplus
    float p = fminf(fmaxf(sp, 0.1f), 100.f);
    g_poles[k] = p;
    g_a[k]  = expf(-p * DF);
    g_aG[k] = expf(-p * DF * 64.f);
}

// ------- Stage 1b: windows + packed coefs (32 blocks) + wsum (blocks 0..3) -------
__global__ __launch_bounds__(256) void k_coef(
    const float* __restrict__ wla, const float* __restrict__ wph)
{
    __shared__ int smL[64], smR[64];
    __shared__ float sp[KM];
    int tid = threadIdx.x;
    int t0 = blockIdx.x * 64;
    float D = g_D;
    if (tid < KM) sp[tid] = g_poles[tid];

    if (tid < 64) {
        int t = t0 + tid;
        float ct = coordf(t);
        int guess = (int)(D * 2047.0f) + 2;
        int hi = SS - 1 - t;
        int j = min(hi, max(0, guess));
        while (j > 0 && fabsf(coordf(t + j) - ct) > D) j--;
        while (j < hi && fabsf(coordf(t + j + 1) - ct) <= D) j++;
        smR[tid] = j;
        hi = t;
        j = min(hi, max(0, guess));
        while (j > 0 && fabsf(coordf(t - j) - ct) > D) j--;
        while (j < hi && fabsf(coordf(t - j - 1) - ct) <= D) j++;
        smL[tid] = j;
    }
    __syncthreads();

    #pragma unroll
    for (int q = 0; q < 8; q++) {
        int i = q * 256 + tid;            // local item in [0, 2048)
        int tl = i >> 5, k = i & 31;
        int t = t0 + tl;
        float ph = sp[k] * DF;
        int mL = smL[tl], mR = smR[tl];
        float em = expm1f(-ph);
        float cL = expm1f(-ph * (float)(mL + 1));
        float cR = expm1f(-ph * (float)(mR + 1));
        float norm = fmaxf(cL / em + cR / em - 1.f, 1e-8f);
        float kn = (float)k * (1.0f / (float)(KM - 1));
        float filt = expf(-4.f * kn * kn);
        float4 pk;
        pk.x = cL + 1.f;                  // a^(mL+1)
        pk.y = cR + 1.f;                  // a^(mR+1)
        pk.z = filt / norm;
        pk.w = __int_as_float(mL | (mR << 16));
        g_pack[t * KM + k] = pk;
    }

    // wsum[k][o] over blocks 0..3 (one (k,o) item per thread)
    if (blockIdx.x < 4) {
        int item = blockIdx.x * 256 + tid;
        int k = item >> 5, o = item & 31;
        float s = 0.f;
        #pragma unroll 8
        for (int c = 0; c < CH; c++) {
            int idx = (k * CH + c) * OC + o;
            float amp = 1.f / (1.f + expf(-wla[idx]));
            s += amp * cosf(wph[idx]);
        }
        g_wsum[k * OC + o] = s;
    }
}

// ---------------- Stage 2: decay scans, grid = (batch, dir) = 16 blocks ----------------
__global__ __launch_bounds__(1024) void k_scan() {
    __shared__ float xs[SS];
    __shared__ float lc[32 * 33];
    int b = blockIdx.x;
    int fwd = (blockIdx.y == 0);
    int tid = threadIdx.x;
    for (int i = tid; i < SS; i += 1024) xs[i] = g_xsum[b * SS + i];

    int j = tid >> 5, k = tid & 31;       // warp = chunk, lane = mode
    float a = g_a[k];
    int t0 = j * 64;
    __syncthreads();

    // pass 1: chunk-local carry
    float s = 0.f;
    if (fwd) {
        #pragma unroll
        for (int i = 0; i < 64; i++) s = fmaf(a, s, xs[t0 + i]);
    } else {
        #pragma unroll
        for (int i = 63; i >= 0; i--) s = fmaf(a, s, xs[t0 + i]);
    }
    lc[j * 33 + k] = s;
    __syncthreads();

    // Kogge-Stone scan over chunks: warp w handles mode k=w, lane = chunk (dir-mapped)
    {
        int w = j;                         // mode index
        int q = fwd ? k : (31 - k);        // chunk handled by this lane
        float v = lc[q * 33 + w];
        float Ap = g_aG[w];                // a^64
        #pragma unroll
        for (int d = 1; d < 32; d <<= 1) {
            float up = __shfl_up_sync(0xffffffffu, v, d);
            if (k >= d) v = fmaf(Ap, up, v);
            Ap = Ap * Ap;
        }
        float inc = __shfl_up_sync(0xffffffffu, v, 1);   // exclusive
        if (k == 0) inc = 0.f;
        __syncthreads();
        lc[q * 33 + w] = inc;
    }
    __syncthreads();

    // pass 2: seeded scan, write P or Q
    float* Zb = (fwd ? g_P : g_Q) + (size_t)b * SS * KM;
    s = lc[j * 33 + k];
    if (fwd) {
        #pragma unroll
        for (int i = 0; i < 64; i++) {
            s = fmaf(a, s, xs[t0 + i]);
            Zb[(size_t)(t0 + i) * KM + k] = s;
        }
    } else {
        #pragma unroll
        for (int i = 63; i >= 0; i--) {
            s = fmaf(a, s, xs[t0 + i]);
            Zb[(size_t)(t0 + i) * KM + k] = s;
        }
    }
}

// ---------------- Stage 3: z tile (64 rows) + GEMV, grid = (32, 8) ----------------
__global__ __launch_bounds__(256) void k_out(float* __restrict__ out) {
    __shared__ float zt[64 * 32];      // [tl][k]
    __shared__ float ws[KM * OC];      // [k][o]
    __shared__ float st[64 * 33];      // [tl][o] padded
    int t0 = blockIdx.x * 64, b = blockIdx.y;
    int tid = threadIdx.x;
    int w = tid >> 5, lane = tid & 31;

    for (int i = tid; i < KM * OC; i += 256) ws[i] = g_wsum[i];

    const float* Pb = g_P + (size_t)b * SS * KM;
    const float* Qb = g_Q + (size_t)b * SS * KM;
    float a = g_a[lane];

    // phase A: rows tl = w + 8q, lane = k
    #pragma unroll
    for (int q = 0; q < 8; q++) {
        int tl = w + 8 * q;
        int t = t0 + tl;
        float4 pk = g_pack[t * KM + lane];
        int mm = __float_as_int(pk.w);
        int mL = mm & 0xffff, mR = mm >> 16;
        float P  = Pb[(size_t)t * KM + lane];
        int tm = t - mL - 1;
        float Pm = (tm >= 0) ? Pb[(size_t)tm * KM + lane] : 0.f;
        float Qp = (t + 1 < SS) ? Qb[(size_t)(t + 1) * KM + lane] : 0.f;
        int tp = t + mR + 1;
        float Qm = (tp < SS) ? Qb[(size_t)tp * KM + lane] : 0.f;
        float L = fmaf(-pk.x, Pm, P);
        float R = fmaf(-pk.y, Qm, a * Qp);
        zt[tl * 32 + lane] = (L + R) * pk.z;
    }
    __syncthreads();

    // phase B: rows tl = w*8..w*8+7, lane = o
    #pragma unroll
    for (int q = 0; q < 8; q++) {
        int tl = w * 8 + q;
        const float4* zr = (const float4*)(zt + tl * 32);
        float acc = 0.f;
        #pragma unroll
        for (int p = 0; p < 8; p++) {
            float4 zv = zr[p];                    // lane-uniform broadcast
            acc = fmaf(zv.x, ws[(p * 4 + 0) * OC + lane], acc);
            acc = fmaf(zv.y, ws[(p * 4 + 1) * OC + lane], acc);
            acc = fmaf(zv.z, ws[(p * 4 + 2) * OC + lane], acc);
            acc = fmaf(zv.w, ws[(p * 4 + 3) * OC + lane], acc);
        }
        st[tl * 33 + lane] = acc;
    }
    __syncthreads();

    // store: thread -> (o = tid/8, 8 consecutive t)
    int o = tid >> 3;
    int i0 = (tid & 7) * 8;
    float* op = out + ((size_t)(b * OC + o)) * SS + t0 + i0;
    #pragma unroll
    for (int ii = 0; ii < 8; ii++) op[ii] = st[(i0 + ii) * 33 + o];
}

extern "C" void kernel_launch(void* const* d_in, const int* in_sizes, int n_in,
                              void* d_out, int out_size) {
    // size-based input resolution
    int ix = -1, ic = -1, idt = -1, iwla = -1, iwph = -1, ilp = -1, ipw = -1, ipb = -1;
    for (int i = 0; i < n_in; i++) {
        int s = in_sizes[i];
        if (s == SB * CH * SS)      { if (ix  < 0) ix  = i; }
        else if (s == SB)           { if (ic  < 0) ic  = i; }
        else if (s == KM * CH * OC) { if (iwla < 0) iwla = i; else if (iwph < 0) iwph = i; }
        else if (s == CH * KM)      { if (ipw < 0) ipw = i; }
        else if (s == KM)           { if (ilp < 0) ilp = i; else if (ipb < 0) ipb = i; }
        else if (s == 1)            { if (idt < 0) idt = i; }
    }
    const float* x   = (const float*)d_in[ix];
    const float* cs  = (const float*)d_in[ic];
    const float* dt  = (const float*)d_in[idt];
    const float* wla = (const float*)d_in[iwla];
    const float* wph = (const float*)d_in[iwph];
    const float* lp  = (const float*)d_in[ilp];
    const float* pw  = (const float*)d_in[ipw];
    const float* pb  = (const float*)d_in[ipb];
    float* out = (float*)d_out;

    k_pre<<<64, 256>>>(x);
    k_poles<<<1, 32>>>(cs, dt, lp, pw, pb);
    k_coef<<<32, 256>>>(wla, wph);
    k_scan<<<dim3(SB, 2), 1024>>>();
    k_out<<<dim3(SS / 64, SB), 256>>>(out);
}

// round 4
// speedup vs baseline: 3.8833x; 1.6245x over previous
#include <cuda_runtime.h>
#include <math.h>

#define SB 8
#define CH 32
#define KM 32
#define OC 32
#define SS 2048
#define DF (1.0f/2047.0f)

// ---- scratch (device globals: allocation-free rule) ----
__device__ __align__(16) float g_xsum[SB*SS];          // [b][s]
__device__ float g_cpart[64*CH];                       // per-block per-channel partials
__device__ float g_P[(size_t)SB*SS*KM];                // [b][t][k] fwd decay scan
__device__ float g_Q[(size_t)SB*SS*KM];                // [b][t][k] bwd decay scan
__device__ __align__(16) float g_wsum[KM*OC];          // [k][o]
__device__ float g_a[KM], g_poles[KM];
__device__ float g_D;

// replicate reference float32 coords: linspace(0,1,2048)
__device__ __forceinline__ float coordf(int i) {
    return (i == SS - 1) ? 1.0f : ((float)i) * DF;
}

// ------- Stage 0: xsum[b][s] + per-channel partials; blocks 0..31 also wsum row -------
__global__ __launch_bounds__(256) void k_pre(const float* __restrict__ x,
                                             const float* __restrict__ wla,
                                             const float* __restrict__ wph) {
    __shared__ __align__(16) float4 sacc[4][64];
    __shared__ float scp[32][2];
    __shared__ float sws[8][32];
    int b = blockIdx.x >> 3, sc = blockIdx.x & 7;
    int tid = threadIdx.x;
    int cg = tid >> 6, s4 = tid & 63;       // channel-group 0..3, s-quad 0..63
    int lane = tid & 31;

    const float4* xb = (const float4*)(x + (size_t)b * CH * SS + sc * 256);
    float4 acc = make_float4(0.f, 0.f, 0.f, 0.f);
    float cp[8];
    #pragma unroll
    for (int j = 0; j < 8; j++) {
        int c = cg * 8 + j;
        float4 v = xb[(size_t)c * (SS / 4) + s4];
        acc.x += v.x; acc.y += v.y; acc.z += v.z; acc.w += v.w;
        cp[j] = (v.x + v.y) + (v.z + v.w);
    }
    sacc[cg][s4] = acc;
    int wic = (tid >> 5) & 1;               // warp-within-cg
    #pragma unroll
    for (int j = 0; j < 8; j++) {
        float w = cp[j];
        w += __shfl_xor_sync(0xffffffffu, w, 16);
        w += __shfl_xor_sync(0xffffffffu, w, 8);
        w += __shfl_xor_sync(0xffffffffu, w, 4);
        w += __shfl_xor_sync(0xffffffffu, w, 2);
        w += __shfl_xor_sync(0xffffffffu, w, 1);
        if (lane == 0) scp[cg * 8 + j][wic] = w;
    }
    __syncthreads();
    if (cg == 0) {
        float4 r = sacc[0][s4], r1 = sacc[1][s4], r2 = sacc[2][s4], r3 = sacc[3][s4];
        r.x += r1.x + r2.x + r3.x;
        r.y += r1.y + r2.y + r3.y;
        r.z += r1.z + r2.z + r3.z;
        r.w += r1.w + r2.w + r3.w;
        ((float4*)(g_xsum + b * SS + sc * 256))[s4] = r;
    }
    if (tid < 32) g_cpart[blockIdx.x * 32 + tid] = scp[tid][0] + scp[tid][1];

    // side job: wsum[k][o] = sum_c sigmoid(wla)*cos(wph), one k-row per block
    if (blockIdx.x < 32) {
        int k = blockIdx.x;
        int cq = tid >> 5;                   // 8 c-groups of 4
        float s = 0.f;
        #pragma unroll
        for (int j = 0; j < 4; j++) {
            int c = cq * 4 + j;
            int idx = (k * CH + c) * OC + lane;
            s += (1.f / (1.f + expf(-wla[idx]))) * cosf(wph[idx]);
        }
        sws[cq][lane] = s;
        __syncthreads();
        if (tid < 32) {
            float t = 0.f;
            #pragma unroll
            for (int j = 0; j < 8; j++) t += sws[j][tid];
            g_wsum[k * OC + tid] = t;
        }
    }
}

// ------- Stage 1: decay scans (poles computed inline), grid = (batch, dir) -------
__global__ __launch_bounds__(1024) void k_scan(
    const float* __restrict__ c_star, const float* __restrict__ dt_star,
    const float* __restrict__ log_poles, const float* __restrict__ pole_w,
    const float* __restrict__ pole_b)
{
    __shared__ __align__(16) float xs[SS];
    __shared__ float lc[32 * 33];
    __shared__ float sxm[32 * 9];           // [c]*9 + r partials, [c]*9+8 = x_mean
    __shared__ float sh_a[KM], sh_aG[KM];
    int b = blockIdx.x;
    int fwd = (blockIdx.y == 0);
    int tid = threadIdx.x;

    if (tid < 512) ((float4*)xs)[tid] = ((const float4*)(g_xsum + b * SS))[tid];

    if (tid < 256) {                        // cpart reduce: c = tid&31, 8 rows each
        int c = tid & 31, r = tid >> 5;
        float s = 0.f;
        #pragma unroll
        for (int j = 0; j < 8; j++) s += g_cpart[(r * 8 + j) * 32 + c];
        sxm[c * 9 + r] = s;
    }
    __syncthreads();
    if (tid < 32) {
        float s = 0.f;
        #pragma unroll
        for (int r = 0; r < 8; r++) s += sxm[tid * 9 + r];
        sxm[tid * 9 + 8] = s * (1.f / (float)(SB * SS));
    }
    __syncthreads();
    if (tid < 32) {
        int k = tid;
        float off = 0.f;
        #pragma unroll 8
        for (int c = 0; c < CH; c++) off += sxm[c * 9 + 8] * pole_w[c * KM + k];
        off = tanhf(off + pole_b[k]);
        float v = log_poles[k] + 0.1f * off;
        float sp = fmaxf(v, 0.f) + log1pf(expf(-fabsf(v)));   // softplus
        float p = fminf(fmaxf(sp, 0.1f), 100.f);
        sh_a[k]  = expf(-p * DF);
        sh_aG[k] = expf(-p * DF * 64.f);
        if (b == 0 && fwd) {
            g_poles[k] = p;
            g_a[k] = sh_a[k];
            if (k == 0) {
                float mx = c_star[0];
                for (int i = 1; i < SB; i++) mx = fmaxf(mx, c_star[i]);
                g_D = mx * dt_star[0];      // CAUSAL_SAFETY = 1
            }
        }
    }
    __syncthreads();

    int j = tid >> 5, k = tid & 31;         // warp = chunk of 64, lane = mode
    float a = sh_a[k];
    const float4* c4 = (const float4*)xs + j * 16;

    // pass 1: chunk-local carry
    float s = 0.f;
    if (fwd) {
        #pragma unroll
        for (int i = 0; i < 16; i++) {
            float4 v = c4[i];
            s = fmaf(a, s, v.x); s = fmaf(a, s, v.y);
            s = fmaf(a, s, v.z); s = fmaf(a, s, v.w);
        }
    } else {
        #pragma unroll
        for (int i = 15; i >= 0; i--) {
            float4 v = c4[i];
            s = fmaf(a, s, v.w); s = fmaf(a, s, v.z);
            s = fmaf(a, s, v.y); s = fmaf(a, s, v.x);
        }
    }
    lc[j * 33 + k] = s;
    __syncthreads();

    // Kogge-Stone over chunks: warp j owns mode w=j (column j), lanes = chunk
    {
        int w = j;
        int q = fwd ? k : (31 - k);
        float v = lc[q * 33 + w];
        float Ap = sh_aG[w];                // a^64
        #pragma unroll
        for (int d = 1; d < 32; d <<= 1) {
            float up = __shfl_up_sync(0xffffffffu, v, d);
            if (k >= d) v = fmaf(Ap, up, v);
            Ap = Ap * Ap;
        }
        float inc = __shfl_up_sync(0xffffffffu, v, 1);   // exclusive
        if (k == 0) inc = 0.f;
        lc[q * 33 + w] = inc;               // column j is warp-private here
    }
    __syncthreads();

    // pass 2: seeded scan, write P or Q
    float* Zb = (fwd ? g_P : g_Q) + (size_t)b * SS * KM;
    s = lc[j * 33 + k];
    int t0 = j * 64;
    if (fwd) {
        #pragma unroll
        for (int i = 0; i < 16; i++) {
            float4 v = c4[i];
            s = fmaf(a, s, v.x); Zb[(size_t)(t0 + 4*i + 0) * KM + k] = s;
            s = fmaf(a, s, v.y); Zb[(size_t)(t0 + 4*i + 1) * KM + k] = s;
            s = fmaf(a, s, v.z); Zb[(size_t)(t0 + 4*i + 2) * KM + k] = s;
            s = fmaf(a, s, v.w); Zb[(size_t)(t0 + 4*i + 3) * KM + k] = s;
        }
    } else {
        #pragma unroll
        for (int i = 15; i >= 0; i--) {
            float4 v = c4[i];
            s = fmaf(a, s, v.w); Zb[(size_t)(t0 + 4*i + 3) * KM + k] = s;
            s = fmaf(a, s, v.z); Zb[(size_t)(t0 + 4*i + 2) * KM + k] = s;
            s = fmaf(a, s, v.y); Zb[(size_t)(t0 + 4*i + 1) * KM + k] = s;
            s = fmaf(a, s, v.x); Zb[(size_t)(t0 + 4*i + 0) * KM + k] = s;
        }
    }
}

// ------- Stage 2: windows + pack (registers) + z tile + GEMV, grid = (64, 8) -------
__global__ __launch_bounds__(256) void k_out(float* __restrict__ out) {
    __shared__ int smL[32], smR[32];
    __shared__ float shp[KM], sha[KM];
    __shared__ __align__(16) float ws[KM * OC];
    __shared__ __align__(16) float zt[32 * 32];
    __shared__ float st[32 * 33];
    int t0 = blockIdx.x * 32, b = blockIdx.y;
    int tid = threadIdx.x;
    int w = tid >> 5, lane = tid & 31;

    ((float4*)ws)[tid] = ((const float4*)g_wsum)[tid];
    if (tid < 32) { shp[tid] = g_poles[tid]; sha[tid] = g_a[tid]; }

    if (tid < 32) {                          // exact float32 window search per row
        float D = g_D;
        int t = t0 + tid;
        float ct = coordf(t);
        int guess = (int)(D * 2047.0f) + 2;
        int hi = SS - 1 - t;
        int j = min(hi, max(0, guess));
        while (j > 0 && fabsf(coordf(t + j) - ct) > D) j--;
        while (j < hi && fabsf(coordf(t + j + 1) - ct) <= D) j++;
        smR[tid] = j;
        hi = t;
        j = min(hi, max(0, guess));
        while (j > 0 && fabsf(coordf(t - j) - ct) > D) j--;
        while (j < hi && fabsf(coordf(t - j - 1) - ct) <= D) j++;
        smL[tid] = j;
    }
    __syncthreads();

    const float* Pb = g_P + (size_t)b * SS * KM;
    const float* Qb = g_Q + (size_t)b * SS * KM;
    float a = sha[lane];
    float ph = shp[lane] * DF;
    float em = expm1f(-ph);
    float kn = (float)lane * (1.0f / (float)(KM - 1));
    float filt = expf(-4.f * kn * kn);

    // phase A: rows tl = w + 8q, lane = k; pack coefs live in registers
    #pragma unroll
    for (int q = 0; q < 4; q++) {
        int tl = w + 8 * q;
        int t = t0 + tl;
        int mL = smL[tl], mR = smR[tl];
        float P  = Pb[(size_t)t * KM + lane];
        int tm = t - mL - 1;
        float Pm = (tm >= 0) ? Pb[(size_t)tm * KM + lane] : 0.f;
        float Qp = (t + 1 < SS) ? Qb[(size_t)(t + 1) * KM + lane] : 0.f;
        int tp = t + mR + 1;
        float Qm = (tp < SS) ? Qb[(size_t)tp * KM + lane] : 0.f;
        float cLe = expm1f(-ph * (float)(mL + 1));
        float cRe = expm1f(-ph * (float)(mR + 1));
        float norm = fmaxf(cLe / em + cRe / em - 1.f, 1e-8f);
        float L = fmaf(-(cLe + 1.f), Pm, P);
        float R = fmaf(-(cRe + 1.f), Qm, a * Qp);
        zt[tl * 32 + lane] = (L + R) * (filt / norm);
    }
    __syncthreads();

    // phase B: GEMV, warp w rows w*4..w*4+3, lane = o
    #pragma unroll
    for (int q = 0; q < 4; q++) {
        int tl = w * 4 + q;
        const float4* zr = (const float4*)(zt + tl * 32);
        float acc = 0.f;
        #pragma unroll
        for (int p = 0; p < 8; p++) {
            float4 zv = zr[p];               // lane-uniform broadcast
            acc = fmaf(zv.x, ws[(p * 4 + 0) * OC + lane], acc);
            acc = fmaf(zv.y, ws[(p * 4 + 1) * OC + lane], acc);
            acc = fmaf(zv.z, ws[(p * 4 + 2) * OC + lane], acc);
            acc = fmaf(zv.w, ws[(p * 4 + 3) * OC + lane], acc);
        }
        st[tl * 33 + lane] = acc;
    }
    __syncthreads();

    // store: thread -> (o = tid/8, 4 consecutive t) as STG.128
    int o = tid >> 3, i0 = (tid & 7) * 4;
    float4 r;
    r.x = st[(i0 + 0) * 33 + o];
    r.y = st[(i0 + 1) * 33 + o];
    r.z = st[(i0 + 2) * 33 + o];
    r.w = st[(i0 + 3) * 33 + o];
    *(float4*)(out + ((size_t)(b * OC + o)) * SS + t0 + i0) = r;
}

extern "C" void kernel_launch(void* const* d_in, const int* in_sizes, int n_in,
                              void* d_out, int out_size) {
    // size-based input resolution
    int ix = -1, ic = -1, idt = -1, iwla = -1, iwph = -1, ilp = -1, ipw = -1, ipb = -1;
    for (int i = 0; i < n_in; i++) {
        int s = in_sizes[i];
        if (s == SB * CH * SS)      { if (ix  < 0) ix  = i; }
        else if (s == SB)           { if (ic  < 0) ic  = i; }
        else if (s == KM * CH * OC) { if (iwla < 0) iwla = i; else if (iwph < 0) iwph = i; }
        else if (s == CH * KM)      { if (ipw < 0) ipw = i; }
        else if (s == KM)           { if (ilp < 0) ilp = i; else if (ipb < 0) ipb = i; }
        else if (s == 1)            { if (idt < 0) idt = i; }
    }
    const float* x   = (const float*)d_in[ix];
    const float* cs  = (const float*)d_in[ic];
    const float* dt  = (const float*)d_in[idt];
    const float* wla = (const float*)d_in[iwla];
    const float* wph = (const float*)d_in[iwph];
    const float* lp  = (const float*)d_in[ilp];
    const float* pw  = (const float*)d_in[ipw];
    const float* pb  = (const float*)d_in[ipb];
    float* out = (float*)d_out;

    k_pre<<<64, 256>>>(x, wla, wph);
    k_scan<<<dim3(SB, 2), 1024>>>(cs, dt, lp, pw, pb);
    k_out<<<dim3(SS / 32, SB), 256>>>(out);
}